// round 2
// baseline (speedup 1.0000x reference)
#include <cuda_runtime.h>
#include <cstdint>

// Per-token int4 quantization:
//   x: [N, H] fp32 (H = 4096)
//   scales[n] = max|x[n,:]| / 7
//   q = clip(rint(x/scale), -8, 7)
//   packed byte = ((q_odd & 0xF) << 4) | (q_even & 0xF)   (as signed int8 value)
//
// Harness output layout (detected via out_size):
//   FLOAT_OUT: [N*H/2 float32 (packed byte values)][N float32 scales]
//   BYTE_OUT : [N*H/2 int8][N float32 scales]

constexpr int H       = 4096;
constexpr int THREADS = 256;
constexpr int PER_THR = H / THREADS;  // 16 floats / thread

template <bool FLOAT_OUT>
__global__ __launch_bounds__(THREADS, 8)
void quant_int4_kernel(const float* __restrict__ x,
                       void* __restrict__ packed_out,
                       float* __restrict__ scales)
{
    const int row = blockIdx.x;
    const int t   = threadIdx.x;

    const float4* xr = reinterpret_cast<const float4*>(x + (size_t)row * H);

    // Each thread: 16 consecutive floats = 4 float4 loads, kept in registers.
    float4 v[PER_THR / 4];
#pragma unroll
    for (int j = 0; j < PER_THR / 4; ++j)
        v[j] = xr[t * (PER_THR / 4) + j];

    // Local max|x|
    float m = 0.0f;
#pragma unroll
    for (int j = 0; j < PER_THR / 4; ++j) {
        m = fmaxf(m, fmaxf(fmaxf(fabsf(v[j].x), fabsf(v[j].y)),
                           fmaxf(fabsf(v[j].z), fabsf(v[j].w))));
    }

    // Warp reduce
#pragma unroll
    for (int o = 16; o > 0; o >>= 1)
        m = fmaxf(m, __shfl_xor_sync(0xffffffffu, m, o));

    __shared__ float smax[THREADS / 32];
    const int warp = t >> 5;
    if ((t & 31) == 0) smax[warp] = m;
    __syncthreads();

    float rowmax = smax[0];
#pragma unroll
    for (int w = 1; w < THREADS / 32; ++w)
        rowmax = fmaxf(rowmax, smax[w]);

    const float scale = rowmax / 7.0f;   // exact fp32, matches reference
    const float inv   = 7.0f / rowmax;   // quantize via multiply

    if (t == 0) scales[row] = scale;

    const float* f = reinterpret_cast<const float*>(v);

    if (FLOAT_OUT) {
        // 16 floats in -> 8 packed bytes -> 8 float32 out (signed byte values)
        float out[8];
#pragma unroll
        for (int i = 0; i < 8; ++i) {
            int q0 = __float2int_rn(f[2 * i + 0] * inv);
            int q1 = __float2int_rn(f[2 * i + 1] * inv);
            q0 = max(-8, min(7, q0));
            q1 = max(-8, min(7, q1));
            int b = (int)(int8_t)(((q1 & 0xF) << 4) | (q0 & 0xF));
            out[i] = (float)b;
        }
        float4* op = reinterpret_cast<float4*>((float*)packed_out + (size_t)row * (H / 2));
        op[2 * t + 0] = make_float4(out[0], out[1], out[2], out[3]);
        op[2 * t + 1] = make_float4(out[4], out[5], out[6], out[7]);
    } else {
        uint32_t lo = 0, hi = 0;
#pragma unroll
        for (int i = 0; i < 8; ++i) {
            int q0 = __float2int_rn(f[2 * i + 0] * inv);
            int q1 = __float2int_rn(f[2 * i + 1] * inv);
            q0 = max(-8, min(7, q0));
            q1 = max(-8, min(7, q1));
            uint32_t b = ((uint32_t)(q1 & 0xF) << 4) | (uint32_t)(q0 & 0xF);
            if (i < 4) lo |= b << (8 * i);
            else       hi |= b << (8 * (i - 4));
        }
        uint2* op = reinterpret_cast<uint2*>((int8_t*)packed_out + (size_t)row * (H / 2));
        op[t] = make_uint2(lo, hi);
    }
}

extern "C" void kernel_launch(void* const* d_in, const int* in_sizes, int n_in,
                              void* d_out, int out_size)
{
    const float* x = (const float*)d_in[0];
    const int rows = in_sizes[0] / H;
    const long long packed_elems = (long long)rows * (H / 2);

    if ((long long)out_size == packed_elems + rows) {
        // float32 layout: packed values as floats, then scales
        float* packed = (float*)d_out;
        float* scales = packed + packed_elems;
        quant_int4_kernel<true><<<rows, THREADS>>>(x, packed, scales);
    } else {
        // int8 layout: packed bytes, then fp32 scales appended as raw bytes
        int8_t* packed = (int8_t*)d_out;
        float*  scales = (float*)(packed + packed_elems);
        quant_int4_kernel<false><<<rows, THREADS>>>(x, packed, scales);
    }
}

// round 3
// speedup vs baseline: 1.0166x; 1.0166x over previous
#include <cuda_runtime.h>
#include <cstdint>

// Per-token int4 quantization:
//   x: [N, H] fp32 (H = 4096)
//   scales[n] = max|x[n,:]| / 7
//   q = clip(rint(x/scale), -8, 7)
//   packed byte = ((q_odd & 0xF) << 4) | (q_even & 0xF)  (as signed int8 value)
//
// Harness output layout (detected via out_size):
//   FLOAT_OUT: [N*H/2 float32 (packed byte values)][N float32 scales]
//   BYTE_OUT : [N*H/2 int8][N float32 scales]
//
// All loads/stores lane-consecutive: thread t handles float4 chunks
// {t, t+256, t+512, t+768} of the row. Each LDG.128 is a contiguous 512B
// warp transaction; each STG.64 (float2 of packed values) is contiguous 256B.

constexpr int H       = 4096;
constexpr int THREADS = 256;
constexpr int CHUNKS  = H / 4 / THREADS;  // 4 float4-chunks per thread

template <bool FLOAT_OUT>
__global__ __launch_bounds__(THREADS, 8)
void quant_int4_kernel(const float* __restrict__ x,
                       void* __restrict__ packed_out,
                       float* __restrict__ scales)
{
    const int row = blockIdx.x;
    const int t   = threadIdx.x;

    const float4* xr = reinterpret_cast<const float4*>(x + (size_t)row * H);

    // Coalesced loads: lane-consecutive float4 per instruction, streaming hint.
    float4 v[CHUNKS];
#pragma unroll
    for (int k = 0; k < CHUNKS; ++k)
        v[k] = __ldcs(&xr[t + THREADS * k]);

    // Local max|x|
    float m = 0.0f;
#pragma unroll
    for (int k = 0; k < CHUNKS; ++k) {
        m = fmaxf(m, fmaxf(fmaxf(fabsf(v[k].x), fabsf(v[k].y)),
                           fmaxf(fabsf(v[k].z), fabsf(v[k].w))));
    }

    // Warp reduce
#pragma unroll
    for (int o = 16; o > 0; o >>= 1)
        m = fmaxf(m, __shfl_xor_sync(0xffffffffu, m, o));

    __shared__ float smax[THREADS / 32];
    if ((t & 31) == 0) smax[t >> 5] = m;
    __syncthreads();

    float rowmax = smax[0];
#pragma unroll
    for (int w = 1; w < THREADS / 32; ++w)
        rowmax = fmaxf(rowmax, smax[w]);

    const float scale = rowmax / 7.0f;   // exact fp32, matches reference
    const float inv   = 7.0f / rowmax;   // quantize via multiply

    if (t == 0) scales[row] = scale;

    // Quantize each float4 chunk -> 2 packed bytes.
    if (FLOAT_OUT) {
        float2* op = reinterpret_cast<float2*>((float*)packed_out + (size_t)row * (H / 2));
#pragma unroll
        for (int k = 0; k < CHUNKS; ++k) {
            int q0 = max(-8, min(7, __float2int_rn(v[k].x * inv)));
            int q1 = max(-8, min(7, __float2int_rn(v[k].y * inv)));
            int q2 = max(-8, min(7, __float2int_rn(v[k].z * inv)));
            int q3 = max(-8, min(7, __float2int_rn(v[k].w * inv)));
            float b0 = (float)(int)(int8_t)(((q1 & 0xF) << 4) | (q0 & 0xF));
            float b1 = (float)(int)(int8_t)(((q3 & 0xF) << 4) | (q2 & 0xF));
            __stcs(&op[t + THREADS * k], make_float2(b0, b1));
        }
    } else {
        uint16_t* op = reinterpret_cast<uint16_t*>((int8_t*)packed_out + (size_t)row * (H / 2));
#pragma unroll
        for (int k = 0; k < CHUNKS; ++k) {
            int q0 = max(-8, min(7, __float2int_rn(v[k].x * inv)));
            int q1 = max(-8, min(7, __float2int_rn(v[k].y * inv)));
            int q2 = max(-8, min(7, __float2int_rn(v[k].z * inv)));
            int q3 = max(-8, min(7, __float2int_rn(v[k].w * inv)));
            uint16_t b = (uint16_t)((((q3 & 0xF) << 4) | (q2 & 0xF)) << 8
                                  | (((q1 & 0xF) << 4) | (q0 & 0xF)));
            op[t + THREADS * k] = b;
        }
    }
}

extern "C" void kernel_launch(void* const* d_in, const int* in_sizes, int n_in,
                              void* d_out, int out_size)
{
    const float* x = (const float*)d_in[0];
    const int rows = in_sizes[0] / H;
    const long long packed_elems = (long long)rows * (H / 2);

    if ((long long)out_size == packed_elems + rows) {
        // float32 layout: packed values as floats, then scales
        float* packed = (float*)d_out;
        float* scales = packed + packed_elems;
        quant_int4_kernel<true><<<rows, THREADS>>>(x, packed, scales);
    } else {
        // int8 layout: packed bytes, then fp32 scales appended as raw bytes
        int8_t* packed = (int8_t*)d_out;
        float*  scales = (float*)(packed + packed_elems);
        quant_int4_kernel<false><<<rows, THREADS>>>(x, packed, scales);
    }
}